// round 17
// baseline (speedup 1.0000x reference)
#include <cuda_runtime.h>
#include <math.h>

#define N_ATOMS 4096
#define NG      128
#define QKV_LD  768

// Scratch (no allocations allowed)
__device__ float g_qkv[N_ATOMS * QKV_LD];   // per row: [0:256)=Q [256:512)=K [512:768)=V
__device__ float g_wct[256 * 256];          // Wct[f][j] = (Wo2 @ Wo1)^T
__device__ float g_bc[256];                 // bc = Wo2 @ bo1
__device__ int   g_off[NG + 1];             // group start offsets (sorted seg ids)
__device__ int   g_ready[32];               // per-128-row-stripe completion (6 j-tiles)
__device__ int   g_offdone;                 // g_off published
__device__ int   g_wdone;                   // wct(32) + bc(8) blocks done -> 40

__device__ __forceinline__ float to_tf32(float x) {
    asm("cvt.rna.tf32.f32 %0, %0;" : "+f"(x));
    return x;
}

__device__ __forceinline__ void mma_tf32(float c[4], const unsigned a[4], const unsigned b[2]) {
    asm volatile(
        "mma.sync.aligned.m16n8k8.row.col.f32.tf32.tf32.f32 "
        "{%0,%1,%2,%3}, {%4,%5,%6,%7}, {%8,%9}, {%0,%1,%2,%3};"
        : "+f"(c[0]), "+f"(c[1]), "+f"(c[2]), "+f"(c[3])
        : "r"(a[0]), "r"(a[1]), "r"(a[2]), "r"(a[3]), "r"(b[0]), "r"(b[1]));
}

__device__ __forceinline__ float silu(float v) {
    return __fdividef(v, 1.0f + __expf(-v));
}

__device__ __forceinline__ float silu_fast(float x) {     // 1 MUFU
    float h = 0.5f * x;
    float t;
    asm("tanh.approx.f32 %0, %1;" : "=f"(t) : "f"(h));
    return h + h * t;
}

// ---------------------------------------------------------------------------
#define PROJ_BLOCKS 192      // 32 stripes x 6 j-tiles (128x128)
#define WC_BLOCKS   32
#define BC_BLOCKS   8
#define ATTN_BLOCKS NG
#define TOTAL_BLOCKS (PROJ_BLOCKS + WC_BLOCKS + BC_BLOCKS + ATTN_BLOCKS)
#define PP       40
#define HSTRIDE  1280        // 32 rows * pitch 40 per head
#define FUSED_SMEM ((2 * 8 * HSTRIDE + 256) * 4)   // K + Q (8 heads) + a_sh = 82944 B

__global__ void zero_flags()
{
    int t = threadIdx.x;
    if (t < 32) g_ready[t] = 0;
    if (t == 32) g_offdone = 0;
    if (t == 33) g_wdone = 0;
}

// ---------------------------------------------------------------------------
// Fused kernel: projection producers + weight-combine + attention consumers,
// synchronized at row-stripe granularity so attention overlaps projection.
// ---------------------------------------------------------------------------
__global__ __launch_bounds__(256, 2) void fused(
        const float* __restrict__ x,
        const float* __restrict__ Wq, const float* __restrict__ bq,
        const float* __restrict__ Wk, const float* __restrict__ bk,
        const float* __restrict__ Wv, const float* __restrict__ bv,
        const float* __restrict__ Wo1, const float* __restrict__ bo1,
        const float* __restrict__ Wo2, const int* __restrict__ seg,
        const float* __restrict__ bo2, float* __restrict__ out)
{
    extern __shared__ float dsh[];
    const int bid = blockIdx.x;
    const int tid = threadIdx.x;

    if (bid < PROJ_BLOCKS) {
        // ====== TF32 projection, BM=128 BN=128, 8 warps of 64x32 ======
        float (*As)[PP] = (float(*)[PP])dsh;               // [128][40]
        float (*Bs)[PP] = (float(*)[PP])(dsh + 128 * PP);  // [128][40]

        const int warp = tid >> 5;
        const int lane = tid & 31;
        const int grp  = lane >> 2;
        const int tig  = lane & 3;
        const int wm   = warp >> 2;        // 0..1 -> rows wm*64
        const int wn   = warp & 3;         // 0..3 -> cols wn*32

        const int stripe = bid / 6;
        const int n0  = stripe * 128;
        const int j0t = (bid % 6) * 128;
        const int sel = j0t >> 8;
        const float* __restrict__ W = (sel == 0) ? Wq : (sel == 1 ? Wk : Wv);
        const float* __restrict__ b = (sel == 0) ? bq : (sel == 1 ? bk : bv);
        const int jl = j0t & 255;          // 0 or 128

        float c[4][4][4] = {};

        for (int k0 = 0; k0 < 256; k0 += 32) {
            #pragma unroll
            for (int it = 0; it < 2; it++) {
                int lin = tid + it * 256;          // 0..511
                int row = lin >> 2;                // 0..127
                int c8  = lin & 3;
                const float* src = &x[(n0 + row) * 256 + k0 + c8 * 8];
                float4 lo = *(const float4*)src;
                float4 hi = *(const float4*)(src + 4);
                *(float4*)&As[row][c8 * 8]     = make_float4(to_tf32(lo.x), to_tf32(hi.x),
                                                             to_tf32(lo.y), to_tf32(hi.y));
                *(float4*)&As[row][c8 * 8 + 4] = make_float4(to_tf32(lo.z), to_tf32(hi.z),
                                                             to_tf32(lo.w), to_tf32(hi.w));
            }
            #pragma unroll
            for (int it = 0; it < 2; it++) {
                int lin = tid + it * 256;
                int row = lin >> 2;                // 0..127 (j-local)
                int c8  = lin & 3;
                const float* src = &W[(jl + row) * 256 + k0 + c8 * 8];
                float4 lo = *(const float4*)src;
                float4 hi = *(const float4*)(src + 4);
                *(float4*)&Bs[row][c8 * 8]     = make_float4(to_tf32(lo.x), to_tf32(hi.x),
                                                             to_tf32(lo.y), to_tf32(hi.y));
                *(float4*)&Bs[row][c8 * 8 + 4] = make_float4(to_tf32(lo.z), to_tf32(hi.z),
                                                             to_tf32(lo.w), to_tf32(hi.w));
            }
            __syncthreads();

            #pragma unroll
            for (int ks = 0; ks < 4; ks++) {
                const int kp = ks * 8 + 2 * tig;
                unsigned bf[4][2];
                #pragma unroll
                for (int nt = 0; nt < 4; nt++) {
                    float2 pB = *(const float2*)&Bs[wn * 32 + nt * 8 + grp][kp];
                    bf[nt][0] = __float_as_uint(pB.x);
                    bf[nt][1] = __float_as_uint(pB.y);
                }
                #pragma unroll
                for (int mt = 0; mt < 4; mt++) {
                    int rb = wm * 64 + mt * 16 + grp;
                    float2 pA0 = *(const float2*)&As[rb    ][kp];
                    float2 pA1 = *(const float2*)&As[rb + 8][kp];
                    unsigned af[4];
                    af[0] = __float_as_uint(pA0.x);
                    af[1] = __float_as_uint(pA1.x);
                    af[2] = __float_as_uint(pA0.y);
                    af[3] = __float_as_uint(pA1.y);
                    #pragma unroll
                    for (int nt = 0; nt < 4; nt++)
                        mma_tf32(c[mt][nt], af, bf[nt]);
                }
            }
            __syncthreads();
        }

        #pragma unroll
        for (int mt = 0; mt < 4; mt++) {
            int r0 = n0 + wm * 64 + mt * 16 + grp;
            int r1 = r0 + 8;
            #pragma unroll
            for (int nt = 0; nt < 4; nt++) {
                int jj  = j0t + wn * 32 + nt * 8 + tig * 2;
                int jlb = jl  + wn * 32 + nt * 8 + tig * 2;
                float b0 = b[jlb], b1 = b[jlb + 1];
                *(float2*)&g_qkv[r0 * QKV_LD + jj] = make_float2(c[mt][nt][0] + b0, c[mt][nt][1] + b1);
                *(float2*)&g_qkv[r1 * QKV_LD + jj] = make_float2(c[mt][nt][2] + b0, c[mt][nt][3] + b1);
            }
        }
        __threadfence();
        __syncthreads();
        if (tid == 0) atomicAdd(&g_ready[stripe], 1);

    } else if (bid < PROJ_BLOCKS + WC_BLOCKS) {
        // ====== Wct tile: 32 f-rows x 64 j-cols, 256 threads ======
        float (*As)[36] = (float(*)[36])dsh;               // As[kk][ff]
        float (*Bs)[68] = (float(*)[68])(dsh + 32 * 36);   // Bs[kk][jj]

        const int t  = bid - PROJ_BLOCKS;
        const int f0 = (t >> 2) * 32;
        const int j0 = (t & 3) * 64;
        const int ti = tid >> 3;       // 0..31 f-row
        const int tj = tid & 7;        // 8 j-cols

        float acc[8] = {};

        for (int k0 = 0; k0 < 256; k0 += 32) {
            {
                int kk = tid >> 3;     // 0..31
                int fq = tid & 7;
                float4 a = *(const float4*)&Wo1[(k0 + kk) * 256 + f0 + fq * 4];
                *(float4*)&As[kk][fq * 4] = a;
            }
            #pragma unroll
            for (int it = 0; it < 2; it++) {
                int lin = tid + it * 256;
                int jj = lin >> 3;     // 0..63
                int kq = lin & 7;
                float4 w = *(const float4*)&Wo2[(j0 + jj) * 256 + k0 + kq * 4];
                Bs[kq * 4 + 0][jj] = w.x;
                Bs[kq * 4 + 1][jj] = w.y;
                Bs[kq * 4 + 2][jj] = w.z;
                Bs[kq * 4 + 3][jj] = w.w;
            }
            __syncthreads();
            #pragma unroll
            for (int kk = 0; kk < 32; kk++) {
                float a = As[kk][ti];
                float4 b4a = *(const float4*)&Bs[kk][tj * 8];
                float4 b4b = *(const float4*)&Bs[kk][tj * 8 + 4];
                acc[0] += a * b4a.x; acc[1] += a * b4a.y;
                acc[2] += a * b4a.z; acc[3] += a * b4a.w;
                acc[4] += a * b4b.x; acc[5] += a * b4b.y;
                acc[6] += a * b4b.z; acc[7] += a * b4b.w;
            }
            __syncthreads();
        }
        #pragma unroll
        for (int v = 0; v < 8; v++)
            g_wct[(f0 + ti) * 256 + j0 + tj * 8 + v] = acc[v];

        __threadfence();
        __syncthreads();
        if (tid == 0) atomicAdd(&g_wdone, 1);

    } else if (bid < PROJ_BLOCKS + WC_BLOCKS + BC_BLOCKS) {
        // ====== bc[j] = Wo2[j,:].bo1 ; block 0 also publishes g_off ======
        const int bb   = bid - PROJ_BLOCKS - WC_BLOCKS;   // 0..7
        const int w    = tid >> 5;
        const int lane = tid & 31;
        #pragma unroll
        for (int u = 0; u < 4; u++) {
            int j = bb * 32 + w * 4 + u;
            float s = 0.0f;
            #pragma unroll
            for (int kc = 0; kc < 8; kc++) {
                int k = kc * 32 + lane;
                s += Wo2[j * 256 + k] * bo1[k];
            }
            #pragma unroll
            for (int off = 16; off; off >>= 1)
                s += __shfl_xor_sync(0xffffffffu, s, off);
            if (lane == 0) g_bc[j] = s;
        }
        if (bb == 0) {
            if (tid < NG) {
                int g = tid;
                int lo = 0, hi = N_ATOMS;
                while (lo < hi) { int mid = (lo + hi) >> 1; if (seg[mid] < g) lo = mid + 1; else hi = mid; }
                g_off[g] = lo;
            }
            if (tid == 0) g_off[NG] = N_ATOMS;
            __threadfence();
            __syncthreads();
            if (tid == 0) *(volatile int*)&g_offdone = 1;
        } else {
            __threadfence();
            __syncthreads();
        }
        if (tid == 0) atomicAdd(&g_wdone, 1);

    } else {
        // ====== Attention consumer: block = group, warp = head ======
        float* Ks   = dsh;                       // [8][32][40] tf32 interleaved
        float* Qs   = dsh + 8 * HSTRIDE;         // [8][32][40]
        float* a_sh = dsh + 16 * HSTRIDE;        // [256]

        const int g    = bid - (PROJ_BLOCKS + WC_BLOCKS + BC_BLOCKS);
        const int w    = tid >> 5;
        const int lane = tid & 31;
        const int grp  = lane >> 2;
        const int tig  = lane & 3;
        const int KB   = w * HSTRIDE;
        const int hb   = w * 32;

        // wait for g_off
        if (tid == 0) { while (*(volatile int*)&g_offdone == 0) {} }
        __syncthreads();
        __threadfence();

        const int start = g_off[g];
        const int end   = g_off[g + 1];
        const int L     = end - start;

        // wait for the row-stripes this group spans
        if (L > 0) {
            int s0 = start >> 7, s1 = (end - 1) >> 7;
            if (tid <= s1 - s0) {
                volatile int* r = g_ready;
                while (r[s0 + tid] < 6) {}
            }
            __syncthreads();
            __threadfence();
        }

        const float4 z4 = make_float4(0.f, 0.f, 0.f, 0.f);
        float out_acc = 0.0f;

        for (int mc = 0; mc < L; mc += 32) {
            const int lm = min(32, L - mc);
            if (mc > 0) __syncthreads();

            // stage K (all heads, tf32 interleaved)
            #pragma unroll
            for (int it = 0; it < 4; it++) {
                int s   = tid + it * 256;       // 0..1023
                int row = s >> 5;
                int c8  = s & 31;
                float4 lo = z4, hi = z4;
                if (row < lm) {
                    const float* src = &g_qkv[(start + mc + row) * QKV_LD + 256 + c8 * 8];
                    lo = *(const float4*)src;
                    hi = *(const float4*)(src + 4);
                }
                float* dst = &Ks[(c8 >> 2) * HSTRIDE + row * 40 + (c8 & 3) * 8];
                ((float4*)dst)[0] = make_float4(to_tf32(lo.x), to_tf32(hi.x),
                                                to_tf32(lo.y), to_tf32(hi.y));
                ((float4*)dst)[1] = make_float4(to_tf32(lo.z), to_tf32(hi.z),
                                                to_tf32(lo.w), to_tf32(hi.w));
            }

            float T0 = 0.f, T1 = 0.f, T2 = 0.f, T3 = 0.f;

            for (int nc = 0; nc < L; nc += 32) {
                const int ln = min(32, L - nc);
                if (nc > 0) __syncthreads();
                #pragma unroll
                for (int it = 0; it < 4; it++) {
                    int s   = tid + it * 256;
                    int row = s >> 5;
                    int c8  = s & 31;
                    float4 lo = z4, hi = z4;
                    if (row < ln) {
                        const float* src = &g_qkv[(start + nc + row) * QKV_LD + c8 * 8];
                        lo = *(const float4*)src;
                        hi = *(const float4*)(src + 4);
                    }
                    float* dst = &Qs[(c8 >> 2) * HSTRIDE + row * 40 + (c8 & 3) * 8];
                    ((float4*)dst)[0] = make_float4(to_tf32(lo.x), to_tf32(hi.x),
                                                    to_tf32(lo.y), to_tf32(hi.y));
                    ((float4*)dst)[1] = make_float4(to_tf32(lo.z), to_tf32(hi.z),
                                                    to_tf32(lo.w), to_tf32(hi.w));
                }
                __syncthreads();

                #pragma unroll
                for (int nt = 0; nt < 4; nt++) {
                    float c[2][4] = {{0.f,0.f,0.f,0.f},{0.f,0.f,0.f,0.f}};
                    #pragma unroll
                    for (int ks = 0; ks < 4; ks++) {
                        const int kp = ks * 8 + 2 * tig;
                        float2 pB = *(const float2*)&Qs[KB + (nt * 8 + grp) * 40 + kp];
                        unsigned bf[2];
                        bf[0] = __float_as_uint(pB.x);
                        bf[1] = __float_as_uint(pB.y);
                        #pragma unroll
                        for (int mt = 0; mt < 2; mt++) {
                            int rb = mt * 16 + grp;
                            float2 pA0 = *(const float2*)&Ks[KB + rb * 40 + kp];
                            float2 pA1 = *(const float2*)&Ks[KB + (rb + 8) * 40 + kp];
                            unsigned af[4];
                            af[0] = __float_as_uint(pA0.x);
                            af[1] = __float_as_uint(pA1.x);
                            af[2] = __float_as_uint(pA0.y);
                            af[3] = __float_as_uint(pA1.y);
                            mma_tf32(c[mt], af, bf);
                        }
                    }
                    #pragma unroll
                    for (int mt = 0; mt < 2; mt++) {
                        float s0 = silu_fast(c[mt][0]) + silu_fast(c[mt][1]);
                        float s1 = silu_fast(c[mt][2]) + silu_fast(c[mt][3]);
                        s0 += __shfl_xor_sync(0xffffffffu, s0, 1);
                        s0 += __shfl_xor_sync(0xffffffffu, s0, 2);
                        s1 += __shfl_xor_sync(0xffffffffu, s1, 1);
                        s1 += __shfl_xor_sync(0xffffffffu, s1, 2);
                        if (mt == 0) { T0 += s0; T1 += s1; }
                        else         { T2 += s0; T3 += s1; }
                    }
                }
            }

            // AV: V read straight from gmem (coalesced 128B rows, L2-hot).
            // Padded m have T=0 so a clamped row index is harmless.
            #pragma unroll
            for (int i = 0; i < 8; i++) {
                float tm0 = __shfl_sync(0xffffffffu, T0, i * 4);
                float tm1 = __shfl_sync(0xffffffffu, T1, i * 4);
                float tm2 = __shfl_sync(0xffffffffu, T2, i * 4);
                float tm3 = __shfl_sync(0xffffffffu, T3, i * 4);
                int r0 = min(start + mc + i,      end - 1);
                int r1 = min(start + mc + i + 8,  end - 1);
                int r2 = min(start + mc + i + 16, end - 1);
                int r3 = min(start + mc + i + 24, end - 1);
                out_acc += tm0 * g_qkv[r0 * QKV_LD + 512 + hb + lane];
                out_acc += tm1 * g_qkv[r1 * QKV_LD + 512 + hb + lane];
                out_acc += tm2 * g_qkv[r2 * QKV_LD + 512 + hb + lane];
                out_acc += tm3 * g_qkv[r3 * QKV_LD + 512 + hb + lane];
            }
        }

        if (L > 0) __syncthreads();
        a_sh[hb + lane] = out_acc;

        // wait for wct/bc producers, then fused output projection
        if (tid == 0) { while (*(volatile int*)&g_wdone < WC_BLOCKS + BC_BLOCKS) {} }
        __syncthreads();
        __threadfence();

        const float cnt = (float)L;
        float acc = 0.0f;
        #pragma unroll 8
        for (int f = 0; f < 256; f++)
            acc += a_sh[f] * g_wct[f * 256 + tid];

        out[g * 256 + tid] = silu(acc + cnt * g_bc[tid] + bo2[tid]);
    }
}

// ---------------------------------------------------------------------------
extern "C" void kernel_launch(void* const* d_in, const int* in_sizes, int n_in,
                              void* d_out, int out_size)
{
    const float* x    = (const float*)d_in[0];
    const int*   elem = (const int*)d_in[1];
    const int*   seg  = elem + N_ATOMS;        // elem_index[1]
    const float* Wq   = (const float*)d_in[2];
    const float* bq   = (const float*)d_in[3];
    const float* Wk   = (const float*)d_in[4];
    const float* bk   = (const float*)d_in[5];
    const float* Wv   = (const float*)d_in[6];
    const float* bv   = (const float*)d_in[7];
    const float* Wo1  = (const float*)d_in[8];
    const float* bo1  = (const float*)d_in[9];
    const float* Wo2  = (const float*)d_in[10];
    const float* bo2  = (const float*)d_in[11];
    float* out = (float*)d_out;

    cudaFuncSetAttribute(fused, cudaFuncAttributeMaxDynamicSharedMemorySize, FUSED_SMEM);

    zero_flags<<<1, 64>>>();
    fused<<<TOTAL_BLOCKS, 256, FUSED_SMEM>>>(x, Wq, bq, Wk, bk, Wv, bv,
                                             Wo1, bo1, Wo2, seg, bo2, out);
}